// round 7
// baseline (speedup 1.0000x reference)
#include <cuda_runtime.h>
#include <cuda_bf16.h>
#include <cstdint>

// Problem constants
#define BB 32      // batch
#define HH 512     // hidden
#define LL 2       // lstm layers
#define TT 20      // text_max_len
#define VV 10000   // vocab
#define SS 49      // spatial (7x7)

// ---------------- device scratch (no allocation allowed) ----------------
__device__ float g_keysT[BB * SS * HH];   // keys  transposed: [b][s][d]
__device__ float g_valsT[BB * SS * HH];   // values transposed: [b][s][d]
__device__ float g_H1[LL * BB * HH];      // h after LSTM (pre-attention-update)
__device__ float g_H2[LL * BB * HH];      // h after attention gate (input to next LSTM)
__device__ float g_C [LL * BB * HH];      // cell state
__device__ float g_q [LL * BB * HH];      // attention query
__device__ float g_attn[LL * BB * HH];    // attention context
__device__ float g_pred0[BB * HH];        // <SOS> embedding
__device__ unsigned long long g_amax[BB]; // packed argmax keys

// ---------------- helpers ----------------
__device__ __forceinline__ float sigmoidf_(float x) { return 1.0f / (1.0f + expf(-x)); }

__device__ __forceinline__ unsigned long long pack_key(float val, int v) {
    unsigned u = __float_as_uint(val);
    u = (u & 0x80000000u) ? ~u : (u | 0x80000000u);   // order-preserving map
    // low word = ~v so that on exact value ties, max key -> smallest v (matches jnp.argmax)
    return (((unsigned long long)u) << 32) | (unsigned)(~(unsigned)v);
}

// ---------------- K1: precompute keys/values (transposed) ----------------
// keysT[b][s][d] = tanh( sum_{s'} chan[b][d][s'] * Wk[s][s'] + bk[s] )
__global__ void k_kv(const float* __restrict__ img,
                     const float* __restrict__ Wk, const float* __restrict__ bk,
                     const float* __restrict__ Wv, const float* __restrict__ bv) {
    __shared__ float wk_s[SS * SS];
    __shared__ float wv_s[SS * SS];
    for (int i = threadIdx.x; i < SS * SS; i += blockDim.x) {
        wk_s[i] = Wk[i];
        wv_s[i] = Wv[i];
    }
    __syncthreads();

    int idx = blockIdx.x * blockDim.x + threadIdx.x;   // exactly B*H*S threads
    int s = idx % SS;
    int d = (idx / SS) % HH;
    int b = idx / (SS * HH);

    const float* chan = img + (b * HH + d) * SS;
    float ak = 0.f, av = 0.f;
    #pragma unroll
    for (int sp = 0; sp < SS; ++sp) {
        float c = chan[sp];
        ak += c * wk_s[s * SS + sp];
        av += c * wv_s[s * SS + sp];
    }
    int o = (b * SS + s) * HH + d;
    g_keysT[o] = tanhf(ak + bk[s]);
    g_valsT[o] = tanhf(av + bv[s]);
}

// ---------------- K2: init state ----------------
__global__ void k_init(const float* __restrict__ pooled,
                       const float* __restrict__ embed,
                       const int* __restrict__ sos_ptr) {
    int idx = blockIdx.x * blockDim.x + threadIdx.x;   // L*B*H threads
    int k = idx % HH;
    int b = (idx / HH) % BB;
    int l = idx / (HH * BB);
    float p = pooled[b * HH + k];
    g_H2[idx] = p;
    g_C[idx]  = p;
    if (l == 0) {
        int sos = sos_ptr[0];
        g_pred0[b * HH + k] = embed[sos * HH + k];
    }
    if (idx < BB) g_amax[idx] = 0ULL;
}

// ---------------- K3: logits GEMM + res column write + fused argmax ----------------
// src_sel: 0 -> g_pred0, 1 -> g_H1 layer 1 (top-layer LSTM output)
__global__ void k_logits(int src_sel,
                         const float* __restrict__ projW, const float* __restrict__ projb,
                         float* __restrict__ res, int t, int do_argmax) {
    __shared__ float xs[128][33];
    __shared__ unsigned long long red[8][32];

    const float* x = src_sel ? (g_H1 + BB * HH) : g_pred0;

    int tid  = threadIdx.x;
    int warp = tid >> 5;
    int lane = tid & 31;                 // lane == batch index
    int v0   = blockIdx.x * 64 + warp * 8;

    float acc[8];
    #pragma unroll
    for (int i = 0; i < 8; ++i) acc[i] = 0.f;

    for (int kt = 0; kt < 4; ++kt) {
        int k0 = kt * 128;
        #pragma unroll
        for (int i = 0; i < 16; ++i) {
            int j  = tid + i * 256;
            int bb = j >> 7;
            int kk = j & 127;
            xs[kk][bb] = x[bb * HH + k0 + kk];
        }
        __syncthreads();

        #pragma unroll 4
        for (int kk = 0; kk < 128; kk += 4) {
            float x0 = xs[kk + 0][lane];
            float x1 = xs[kk + 1][lane];
            float x2 = xs[kk + 2][lane];
            float x3 = xs[kk + 3][lane];
            #pragma unroll
            for (int vi = 0; vi < 8; ++vi) {
                int v = v0 + vi;
                if (v < VV) {
                    float4 w = *(const float4*)(projW + v * HH + k0 + kk);
                    acc[vi] += x0 * w.x + x1 * w.y + x2 * w.z + x3 * w.w;
                }
            }
        }
        __syncthreads();
    }

    unsigned long long best = 0ULL;
    #pragma unroll
    for (int vi = 0; vi < 8; ++vi) {
        int v = v0 + vi;
        if (v < VV) {
            float val = acc[vi] + projb[v];
            res[lane * (VV * TT) + v * TT + t] = val;
            unsigned long long key = pack_key(val, v);
            if (key > best) best = key;
        }
    }

    if (do_argmax) {
        red[warp][lane] = best;
        __syncthreads();
        if (warp == 0) {
            unsigned long long m = red[0][lane];
            #pragma unroll
            for (int w = 1; w < 8; ++w) {
                unsigned long long k2 = red[w][lane];
                if (k2 > m) m = k2;
            }
            atomicMax(&g_amax[lane], m);
        }
    }
}

// ---------------- K4: LSTM cell (one layer) ----------------
// xsel: 0 -> g_pred0 ; 1 -> embed[argmax] ; 2 -> g_H1 layer 0
__global__ void k_lstm(int xsel, const float* __restrict__ embed,
                       const float* __restrict__ Wih, const float* __restrict__ Whh,
                       const float* __restrict__ bih, const float* __restrict__ bhh,
                       int layer) {
    __shared__ float xs[128][33];
    __shared__ float hs[128][33];
    __shared__ int   vsel[BB];

    int tid  = threadIdx.x;   // 128 threads
    int warp = tid >> 5;
    int lane = tid & 31;      // lane == batch
    int u    = blockIdx.x * 4 + warp;   // hidden unit

    // reset argmax accumulator between steps (after layer-0 consumed it)
    if (layer == 1 && blockIdx.x == 0 && tid < BB) g_amax[tid] = 0ULL;

    if (xsel == 1 && tid < BB) vsel[tid] = (int)(~(unsigned)(g_amax[tid] & 0xffffffffULL));
    __syncthreads();

    const float* h_prev = g_H2 + layer * BB * HH;
    const float* x_base = (xsel == 2) ? g_H1 : g_pred0;

    const float* wih = Wih + layer * 4 * HH * HH + u * HH;
    const float* whh = Whh + layer * 4 * HH * HH + u * HH;
    const int ROW = HH * HH;  // offset between gate blocks (512 rows * 512)

    float ai = 0.f, af = 0.f, ag = 0.f, ao = 0.f;

    for (int kt = 0; kt < 4; ++kt) {
        int k0 = kt * 128;
        #pragma unroll
        for (int i = 0; i < 32; ++i) {
            int j  = tid + i * 128;
            int bb = j >> 7;       // == i here (tid<128) but keep general
            int kk = j & 127;
            float xv;
            if (xsel == 1) xv = embed[(size_t)vsel[bb] * HH + k0 + kk];
            else           xv = x_base[bb * HH + k0 + kk];
            xs[kk][bb] = xv;
            hs[kk][bb] = h_prev[bb * HH + k0 + kk];
        }
        __syncthreads();

        #pragma unroll 4
        for (int kk = 0; kk < 128; kk += 4) {
            float x0 = xs[kk+0][lane], x1 = xs[kk+1][lane], x2 = xs[kk+2][lane], x3 = xs[kk+3][lane];
            float h0 = hs[kk+0][lane], h1 = hs[kk+1][lane], h2 = hs[kk+2][lane], h3 = hs[kk+3][lane];
            int kg = k0 + kk;
            float4 w;
            w = *(const float4*)(wih + 0*ROW + kg); ai += x0*w.x + x1*w.y + x2*w.z + x3*w.w;
            w = *(const float4*)(whh + 0*ROW + kg); ai += h0*w.x + h1*w.y + h2*w.z + h3*w.w;
            w = *(const float4*)(wih + 1*ROW + kg); af += x0*w.x + x1*w.y + x2*w.z + x3*w.w;
            w = *(const float4*)(whh + 1*ROW + kg); af += h0*w.x + h1*w.y + h2*w.z + h3*w.w;
            w = *(const float4*)(wih + 2*ROW + kg); ag += x0*w.x + x1*w.y + x2*w.z + x3*w.w;
            w = *(const float4*)(whh + 2*ROW + kg); ag += h0*w.x + h1*w.y + h2*w.z + h3*w.w;
            w = *(const float4*)(wih + 3*ROW + kg); ao += x0*w.x + x1*w.y + x2*w.z + x3*w.w;
            w = *(const float4*)(whh + 3*ROW + kg); ao += h0*w.x + h1*w.y + h2*w.z + h3*w.w;
        }
        __syncthreads();
    }

    const float* bi = bih + layer * 4 * HH;
    const float* bh = bhh + layer * 4 * HH;
    ai += bi[u]          + bh[u];
    af += bi[HH + u]     + bh[HH + u];
    ag += bi[2*HH + u]   + bh[2*HH + u];
    ao += bi[3*HH + u]   + bh[3*HH + u];

    int co = layer * BB * HH + lane * HH + u;
    float c_old = g_C[co];
    float c2 = sigmoidf_(af) * c_old + sigmoidf_(ai) * tanhf(ag);
    float hv = sigmoidf_(ao) * tanhf(c2);
    g_C[co]  = c2;
    g_H1[co] = hv;
}

// ---------------- K5: generic 32xN (N=512) GEMM + tanh ----------------
// MODE 0 (q):      out = g_q,  A = g_H1,   W1 = Wq   (row stride 512), bias = bq
// MODE 1 (h-upd):  out = g_H2, A = g_attn, B = g_H1, W = hattW (row stride 1024,
//                  first half for attn, second half for h), bias = hattb
template <int MODE>
__global__ void k_gemm_tanh(const float* __restrict__ W1, const float* __restrict__ bias) {
    __shared__ float as_[128][33];
    __shared__ float bs_[128][33];

    int l    = blockIdx.y;
    int tid  = threadIdx.x;    // 128
    int warp = tid >> 5;
    int lane = tid & 31;       // batch
    int j    = blockIdx.x * 4 + warp;

    const float* A  = (MODE == 0 ? g_H1   : g_attn) + l * BB * HH;
    const float* Bm = g_H1 + l * BB * HH;                 // used only in MODE 1
    float*       out = (MODE == 0 ? g_q : g_H2) + l * BB * HH;
    const int WS = (MODE == 0) ? HH : 2 * HH;

    float acc = 0.f;
    for (int kt = 0; kt < 4; ++kt) {
        int k0 = kt * 128;
        #pragma unroll
        for (int i = 0; i < 32; ++i) {
            int jj = tid + i * 128;
            int bb = jj >> 7;
            int kk = jj & 127;
            as_[kk][bb] = A[bb * HH + k0 + kk];
            if (MODE == 1) bs_[kk][bb] = Bm[bb * HH + k0 + kk];
        }
        __syncthreads();

        #pragma unroll 4
        for (int kk = 0; kk < 128; kk += 4) {
            float a0 = as_[kk+0][lane], a1 = as_[kk+1][lane], a2 = as_[kk+2][lane], a3 = as_[kk+3][lane];
            int kg = k0 + kk;
            float4 w = *(const float4*)(W1 + j * WS + kg);
            acc += a0*w.x + a1*w.y + a2*w.z + a3*w.w;
            if (MODE == 1) {
                float b0 = bs_[kk+0][lane], b1 = bs_[kk+1][lane], b2 = bs_[kk+2][lane], b3 = bs_[kk+3][lane];
                float4 w2 = *(const float4*)(W1 + j * WS + HH + kg);
                acc += b0*w2.x + b1*w2.y + b2*w2.z + b3*w2.w;
            }
        }
        __syncthreads();
    }

    out[lane * HH + j] = tanhf(acc + bias[j]);
}

// ---------------- K6: attention scores + softmax + context ----------------
__global__ void k_attn() {
    __shared__ float qs[HH];
    __shared__ float ssh[SS];
    __shared__ float wsh[SS];

    int b = blockIdx.x;
    int l = blockIdx.y;
    int tid = threadIdx.x;     // 256
    int warp = tid >> 5;
    int lane = tid & 31;

    qs[tid]       = g_q[(l * BB + b) * HH + tid];
    qs[tid + 256] = g_q[(l * BB + b) * HH + tid + 256];
    __syncthreads();

    // scores[s] = (sum_d q[d] * keysT[b][s][d]) / 7
    for (int s = warp; s < SS; s += 8) {
        const float* krow = g_keysT + (b * SS + s) * HH;
        float sum = 0.f;
        #pragma unroll
        for (int i = 0; i < 4; ++i) {
            float4 kv = *(const float4*)(krow + lane * 4 + i * 128);
            float4 qv = *(const float4*)(qs   + lane * 4 + i * 128);
            sum += kv.x*qv.x + kv.y*qv.y + kv.z*qv.z + kv.w*qv.w;
        }
        #pragma unroll
        for (int off = 16; off; off >>= 1)
            sum += __shfl_xor_sync(0xffffffffu, sum, off);
        if (lane == 0) ssh[s] = sum / 7.0f;
    }
    __syncthreads();

    // softmax over 49 (warp 0)
    if (tid < 32) {
        float v0 = ssh[tid];
        float v1 = (tid + 32 < SS) ? ssh[tid + 32] : -3.4e38f;
        float m = fmaxf(v0, v1);
        #pragma unroll
        for (int off = 16; off; off >>= 1)
            m = fmaxf(m, __shfl_xor_sync(0xffffffffu, m, off));
        float e0 = expf(v0 - m);
        float e1 = (tid + 32 < SS) ? expf(v1 - m) : 0.f;
        float s = e0 + e1;
        #pragma unroll
        for (int off = 16; off; off >>= 1)
            s += __shfl_xor_sync(0xffffffffu, s, off);
        wsh[tid] = e0 / s;
        if (tid + 32 < SS) wsh[tid + 32] = e1 / s;
    }
    __syncthreads();

    // attn[d] = sum_s w[s] * valsT[b][s][d]
    #pragma unroll
    for (int r = 0; r < 2; ++r) {
        int d = tid + r * 256;
        float acc = 0.f;
        #pragma unroll
        for (int s = 0; s < SS; ++s)
            acc += wsh[s] * g_valsT[(b * SS + s) * HH + d];
        g_attn[(l * BB + b) * HH + d] = acc;
    }
}

// ---------------- host launcher ----------------
extern "C" void kernel_launch(void* const* d_in, const int* in_sizes, int n_in,
                              void* d_out, int out_size) {
    const float* img    = (const float*)d_in[0];
    const float* pooled = (const float*)d_in[1];
    const float* embed  = (const float*)d_in[2];
    const float* Wq     = (const float*)d_in[3];
    const float* bq     = (const float*)d_in[4];
    const float* Wk     = (const float*)d_in[5];
    const float* bk     = (const float*)d_in[6];
    const float* Wv     = (const float*)d_in[7];
    const float* bv     = (const float*)d_in[8];
    const float* Wih    = (const float*)d_in[9];
    const float* Whh    = (const float*)d_in[10];
    const float* bih    = (const float*)d_in[11];
    const float* bhh    = (const float*)d_in[12];
    const float* projW  = (const float*)d_in[13];
    const float* projb  = (const float*)d_in[14];
    const float* hattW  = (const float*)d_in[15];
    const float* hattb  = (const float*)d_in[16];
    const int*   sosp   = (const int*)d_in[17];
    float* res = (float*)d_out;

    // keys/values precompute + state init (independent, but same stream is fine)
    k_kv<<<(BB * HH * SS) / 256, 256>>>(img, Wk, bk, Wv, bv);
    k_init<<<(LL * BB * HH) / 256, 256>>>(pooled, embed, sosp);

    // res[:, :, 0] from <SOS> embedding (no argmax)
    k_logits<<<157, 256>>>(0, projW, projb, res, 0, 0);

    for (int i = 0; i < TT - 1; ++i) {
        // layer 0: input = emb (SOS at i==0, else greedy token embedding)
        k_lstm<<<128, 128>>>(i == 0 ? 0 : 1, embed, Wih, Whh, bih, bhh, 0);
        // layer 1: input = layer-0 new hidden (also resets g_amax for this step)
        k_lstm<<<128, 128>>>(2, embed, Wih, Whh, bih, bhh, 1);
        // logits of top-layer output -> res[:, :, i+1]; argmax -> next token
        k_logits<<<157, 256>>>(1, projW, projb, res, i + 1, (i < TT - 2) ? 1 : 0);

        if (i < TT - 2) {
            // attention-gated hidden update (skipped on last step: result unused)
            k_gemm_tanh<0><<<dim3(128, LL), 128>>>(Wq, bq);
            k_attn<<<dim3(BB, LL), 256>>>();
            k_gemm_tanh<1><<<dim3(128, LL), 128>>>(hattW, hattb);
        }
    }
}

// round 8
// speedup vs baseline: 2.7092x; 2.7092x over previous
#include <cuda_runtime.h>
#include <cuda_bf16.h>
#include <cstdint>

// Problem constants
#define BB 32      // batch
#define HH 512     // hidden
#define LL 2       // lstm layers
#define TT 20      // text_max_len
#define VV 10000   // vocab
#define SS 49      // spatial (7x7)

// ---------------- device scratch (no allocation allowed) ----------------
__device__ float g_keysT[BB * SS * HH];   // keys  transposed: [b][s][d]
__device__ float g_valsT[BB * SS * HH];   // values transposed: [b][s][d]
__device__ float g_H1[LL * BB * HH];      // h after LSTM (pre-attention-update)
__device__ float g_H2[LL * BB * HH];      // h after attention gate (input to next LSTM)
__device__ float g_C [LL * BB * HH];      // cell state
__device__ float g_q [LL * BB * HH];      // attention query
__device__ float g_attn[LL * BB * HH];    // attention context
__device__ float g_pred0[BB * HH];        // <SOS> embedding
__device__ unsigned long long g_amax[BB]; // packed argmax keys

// ---------------- helpers ----------------
__device__ __forceinline__ float sigmoidf_(float x) { return 1.0f / (1.0f + expf(-x)); }

__device__ __forceinline__ unsigned long long pack_key(float val, int v) {
    unsigned u = __float_as_uint(val);
    u = (u & 0x80000000u) ? ~u : (u | 0x80000000u);   // order-preserving map
    // low word = ~v so that on exact value ties, max key -> smallest v (matches jnp.argmax)
    return (((unsigned long long)u) << 32) | (unsigned)(~(unsigned)v);
}

__device__ __forceinline__ float dot4(float4 a, float4 b) {
    return a.x*b.x + a.y*b.y + a.z*b.z + a.w*b.w;
}

// ---------------- K1: precompute keys/values (transposed) ----------------
__global__ void k_kv(const float* __restrict__ img,
                     const float* __restrict__ Wk, const float* __restrict__ bk,
                     const float* __restrict__ Wv, const float* __restrict__ bv) {
    __shared__ float wk_s[SS * SS];
    __shared__ float wv_s[SS * SS];
    for (int i = threadIdx.x; i < SS * SS; i += blockDim.x) {
        wk_s[i] = Wk[i];
        wv_s[i] = Wv[i];
    }
    __syncthreads();

    int idx = blockIdx.x * blockDim.x + threadIdx.x;   // exactly B*H*S threads
    int s = idx % SS;
    int d = (idx / SS) % HH;
    int b = idx / (SS * HH);

    const float* chan = img + (b * HH + d) * SS;
    float ak = 0.f, av = 0.f;
    #pragma unroll
    for (int sp = 0; sp < SS; ++sp) {
        float c = chan[sp];
        ak += c * wk_s[s * SS + sp];
        av += c * wv_s[s * SS + sp];
    }
    int o = (b * SS + s) * HH + d;
    g_keysT[o] = tanhf(ak + bk[s]);
    g_valsT[o] = tanhf(av + bv[s]);
}

// ---------------- K2: init state ----------------
__global__ void k_init(const float* __restrict__ pooled,
                       const float* __restrict__ embed,
                       const int* __restrict__ sos_ptr) {
    int idx = blockIdx.x * blockDim.x + threadIdx.x;   // L*B*H threads
    int k = idx % HH;
    int b = (idx / HH) % BB;
    int l = idx / (HH * BB);
    float p = pooled[b * HH + k];
    g_H2[idx] = p;
    g_C[idx]  = p;
    if (l == 0) {
        int sos = sos_ptr[0];
        g_pred0[b * HH + k] = embed[sos * HH + k];
    }
    if (idx < BB) g_amax[idx] = 0ULL;
}

// ---------------- K3: logits GEMM + res column write + fused argmax ----------------
// 256 threads, 8 warps; block covers 64 vocab rows (8 per warp), lane = batch.
// Weights staged coalesced through shared; K processed in 8 chunks of 64.
__global__ void k_logits(int src_sel,
                         const float* __restrict__ projW, const float* __restrict__ projb,
                         float* __restrict__ res, int t, int do_argmax) {
    __shared__ float4 xs4[32][17];            // [b][quad], odd stride -> conflict-free
    __shared__ float4 wt[64][16];             // [row][quad]  (64 rows x 64 k)
    __shared__ unsigned long long red[8][32];

    const float* x = src_sel ? (g_H1 + BB * HH) : g_pred0;

    int tid  = threadIdx.x;
    int warp = tid >> 5;
    int lane = tid & 31;                 // lane == batch
    int v0   = blockIdx.x * 64;

    float acc[8];
    #pragma unroll
    for (int i = 0; i < 8; ++i) acc[i] = 0.f;

    for (int kt = 0; kt < 8; ++kt) {
        int k0 = kt * 64;
        // stage x: 32 b x 16 quads = 512 float4, 2 per thread (coalesced)
        #pragma unroll
        for (int i = 0; i < 2; ++i) {
            int fid = tid + i * 256;
            int b = fid >> 4, q = fid & 15;
            xs4[b][q] = *(const float4*)(x + b * HH + k0 + q * 4);
        }
        // stage weights: 64 rows x 16 quads = 1024 float4, 4 per thread (coalesced)
        #pragma unroll
        for (int i = 0; i < 4; ++i) {
            int fid = tid + i * 256;
            int r = fid >> 4, c = fid & 15;
            int v = v0 + r; if (v >= VV) v = VV - 1;
            wt[r][c] = *(const float4*)(projW + v * HH + k0 + c * 4);
        }
        __syncthreads();

        int r0 = warp * 8;
        #pragma unroll
        for (int q = 0; q < 16; ++q) {
            float4 xv = xs4[lane][q];
            #pragma unroll
            for (int vi = 0; vi < 8; ++vi) {
                float4 w = wt[r0 + vi][q];     // broadcast LDS
                acc[vi] += dot4(w, xv);
            }
        }
        __syncthreads();
    }

    unsigned long long best = 0ULL;
    #pragma unroll
    for (int vi = 0; vi < 8; ++vi) {
        int v = v0 + warp * 8 + vi;
        if (v < VV) {
            float val = acc[vi] + projb[v];
            res[lane * (VV * TT) + v * TT + t] = val;
            unsigned long long key = pack_key(val, v);
            if (key > best) best = key;
        }
    }

    if (do_argmax) {
        red[warp][lane] = best;
        __syncthreads();
        if (warp == 0) {
            unsigned long long m = red[0][lane];
            #pragma unroll
            for (int w = 1; w < 8; ++w) {
                unsigned long long k2 = red[w][lane];
                if (k2 > m) m = k2;
            }
            atomicMax(&g_amax[lane], m);
        }
    }
}

// ---------------- K4: LSTM cell (one layer) ----------------
// 512 threads = 16 warps; block handles 4 hidden units; warp = (unit_local, gate).
// xsel: 0 -> g_pred0 ; 1 -> embed[argmax] ; 2 -> g_H1 layer 0
__global__ void k_lstm(int xsel, const float* __restrict__ embed,
                       const float* __restrict__ Wih, const float* __restrict__ Whh,
                       const float* __restrict__ bih, const float* __restrict__ bhh,
                       int layer) {
    __shared__ float4 xs4[32][33];     // [b][quad of 128-k tile]
    __shared__ float4 hs4[32][33];
    __shared__ float4 wt[32][16];      // 32 rows (u,g,mat) x 16 quads (64 k)
    __shared__ float  gsh[4][4][32];   // [unit][gate][b]
    __shared__ int    vsel[BB];

    int tid  = threadIdx.x;   // 512
    int warp = tid >> 5;
    int lane = tid & 31;      // lane == batch
    int uw   = warp >> 2;     // unit local 0..3
    int g    = warp & 3;      // gate 0..3 (i,f,g,o)
    int u    = blockIdx.x * 4 + uw;

    // reset argmax accumulator between steps (after layer-0 consumed it)
    if (layer == 1 && blockIdx.x == 0 && tid < BB) g_amax[tid] = 0ULL;
    if (xsel == 1 && tid < BB) vsel[tid] = (int)(~(unsigned)(g_amax[tid] & 0xffffffffULL));
    __syncthreads();

    const float* h_prev = g_H2 + layer * BB * HH;
    const float* x_base = (xsel == 2) ? g_H1 : g_pred0;
    const float* WihL = Wih + layer * 4 * HH * HH;
    const float* WhhL = Whh + layer * 4 * HH * HH;

    float a0 = 0.f, a1 = 0.f, a2 = 0.f, a3 = 0.f;   // 4 independent chains

    for (int kt = 0; kt < 4; ++kt) {
        int k0 = kt * 128;
        // stage x and h: 32 b x 32 quads = 1024 float4 each, 2 per thread
        #pragma unroll
        for (int i = 0; i < 2; ++i) {
            int fid = tid + i * 512;
            int b = fid >> 5, q = fid & 31;
            const float* xsrc = (xsel == 1) ? (embed + (size_t)vsel[b] * HH)
                                            : (x_base + b * HH);
            xs4[b][q] = *(const float4*)(xsrc + k0 + q * 4);
            hs4[b][q] = *(const float4*)(h_prev + b * HH + k0 + q * 4);
        }

        #pragma unroll
        for (int half = 0; half < 2; ++half) {
            int kh = k0 + half * 64;
            // stage weights: 32 rows x 16 quads = 512 float4, 1 per thread
            {
                int r = tid >> 4, c = tid & 15;
                int uu = r >> 3, gg = (r >> 1) & 3, m = r & 1;
                const float* base = (m ? WhhL : WihL)
                                    + (gg * HH + blockIdx.x * 4 + uu) * HH + kh;
                wt[r][c] = *(const float4*)(base + c * 4);
            }
            __syncthreads();

            int wr_x = (uw << 3) | (g << 1);
            int wr_h = wr_x | 1;
            int qb = half * 16;
            #pragma unroll
            for (int q = 0; q < 16; ++q) {
                float4 wx = wt[wr_x][q];           // broadcast
                float4 wh = wt[wr_h][q];
                float4 xv = xs4[lane][qb + q];
                float4 hv = hs4[lane][qb + q];
                a0 += wx.x * xv.x;  a1 += wx.y * xv.y;
                a2 += wx.z * xv.z;  a3 += wx.w * xv.w;
                a0 += wh.x * hv.x;  a1 += wh.y * hv.y;
                a2 += wh.z * hv.z;  a3 += wh.w * hv.w;
            }
            __syncthreads();
        }
    }

    float acc = (a0 + a1) + (a2 + a3)
              + bih[layer * 4 * HH + g * HH + u]
              + bhh[layer * 4 * HH + g * HH + u];
    gsh[uw][g][lane] = acc;
    __syncthreads();

    if (warp < 4) {   // finalize: warp = unit, lane = batch
        int u2 = blockIdx.x * 4 + warp;
        float vi = gsh[warp][0][lane];
        float vf = gsh[warp][1][lane];
        float vg = gsh[warp][2][lane];
        float vo = gsh[warp][3][lane];
        int co = layer * BB * HH + lane * HH + u2;
        float c2 = sigmoidf_(vf) * g_C[co] + sigmoidf_(vi) * tanhf(vg);
        g_C[co]  = c2;
        g_H1[co] = sigmoidf_(vo) * tanhf(c2);
    }
}

// ---------------- K5: 32xN (N=512) GEMM + tanh, staged weights ----------------
// 256 threads, 8 warps, 2 output units per warp -> 16 per block, grid (32, L).
// MODE 0 (q):      out = g_q,  in = g_H1,               W row stride 512
// MODE 1 (h-upd):  out = g_H2, in = [g_attn ; g_H1],    W row stride 1024
template <int MODE>
__global__ void k_gemm_tanh(const float* __restrict__ W1, const float* __restrict__ bias) {
    __shared__ float4 as4[32][17];
    __shared__ float4 bs4[32][17];
    __shared__ float4 wt[16][2][16];   // [jrow][half][quad]

    int l    = blockIdx.y;
    int tid  = threadIdx.x;    // 256
    int warp = tid >> 5;
    int lane = tid & 31;       // batch
    int j0   = blockIdx.x * 16;

    const float* A  = (MODE ? g_attn : g_H1) + l * BB * HH;
    const float* Bm = g_H1 + l * BB * HH;
    float*      out = (MODE ? g_H2 : g_q) + l * BB * HH;
    const int WS = MODE ? 2 * HH : HH;

    float4 acc[2];
    acc[0] = make_float4(0.f, 0.f, 0.f, 0.f);
    acc[1] = make_float4(0.f, 0.f, 0.f, 0.f);

    for (int kt = 0; kt < 8; ++kt) {
        int k0 = kt * 64;
        #pragma unroll
        for (int i = 0; i < 2; ++i) {
            int fid = tid + i * 256;
            int b = fid >> 4, q = fid & 15;
            as4[b][q] = *(const float4*)(A + b * HH + k0 + q * 4);
            if (MODE) bs4[b][q] = *(const float4*)(Bm + b * HH + k0 + q * 4);
        }
        // weights: 16 rows x (1 or 2 halves) x 16 quads
        {
            int r = tid >> 4, c = tid & 15;
            wt[r][0][c] = *(const float4*)(W1 + (j0 + r) * WS + k0 + c * 4);
            if (MODE) wt[r][1][c] = *(const float4*)(W1 + (j0 + r) * WS + HH + k0 + c * 4);
        }
        __syncthreads();

        int jr = warp * 2;
        #pragma unroll
        for (int q = 0; q < 16; ++q) {
            float4 av = as4[lane][q];
            float4 bv;
            if (MODE) bv = bs4[lane][q];
            #pragma unroll
            for (int jj = 0; jj < 2; ++jj) {
                float4 w = wt[jr + jj][0][q];
                acc[jj].x += w.x * av.x;  acc[jj].y += w.y * av.y;
                acc[jj].z += w.z * av.z;  acc[jj].w += w.w * av.w;
                if (MODE) {
                    float4 w2 = wt[jr + jj][1][q];
                    acc[jj].x += w2.x * bv.x;  acc[jj].y += w2.y * bv.y;
                    acc[jj].z += w2.z * bv.z;  acc[jj].w += w2.w * bv.w;
                }
            }
        }
        __syncthreads();
    }

    #pragma unroll
    for (int jj = 0; jj < 2; ++jj) {
        int j = j0 + warp * 2 + jj;
        float s = (acc[jj].x + acc[jj].y) + (acc[jj].z + acc[jj].w);
        out[lane * HH + j] = tanhf(s + bias[j]);
    }
}

// ---------------- K6: attention scores + softmax + context ----------------
__global__ void k_attn() {
    __shared__ float qs[HH];
    __shared__ float ssh[SS];
    __shared__ float wsh[SS];

    int b = blockIdx.x;
    int l = blockIdx.y;
    int tid = threadIdx.x;     // 256
    int warp = tid >> 5;
    int lane = tid & 31;

    qs[tid]       = g_q[(l * BB + b) * HH + tid];
    qs[tid + 256] = g_q[(l * BB + b) * HH + tid + 256];
    __syncthreads();

    for (int s = warp; s < SS; s += 8) {
        const float* krow = g_keysT + (b * SS + s) * HH;
        float sum = 0.f;
        #pragma unroll
        for (int i = 0; i < 4; ++i) {
            float4 kv = *(const float4*)(krow + lane * 4 + i * 128);
            float4 qv = *(const float4*)(qs   + lane * 4 + i * 128);
            sum += kv.x*qv.x + kv.y*qv.y + kv.z*qv.z + kv.w*qv.w;
        }
        #pragma unroll
        for (int off = 16; off; off >>= 1)
            sum += __shfl_xor_sync(0xffffffffu, sum, off);
        if (lane == 0) ssh[s] = sum / 7.0f;
    }
    __syncthreads();

    if (tid < 32) {
        float v0 = ssh[tid];
        float v1 = (tid + 32 < SS) ? ssh[tid + 32] : -3.4e38f;
        float m = fmaxf(v0, v1);
        #pragma unroll
        for (int off = 16; off; off >>= 1)
            m = fmaxf(m, __shfl_xor_sync(0xffffffffu, m, off));
        float e0 = expf(v0 - m);
        float e1 = (tid + 32 < SS) ? expf(v1 - m) : 0.f;
        float s = e0 + e1;
        #pragma unroll
        for (int off = 16; off; off >>= 1)
            s += __shfl_xor_sync(0xffffffffu, s, off);
        wsh[tid] = e0 / s;
        if (tid + 32 < SS) wsh[tid + 32] = e1 / s;
    }
    __syncthreads();

    #pragma unroll
    for (int r = 0; r < 2; ++r) {
        int d = tid + r * 256;
        float acc = 0.f;
        #pragma unroll
        for (int s = 0; s < SS; ++s)
            acc += wsh[s] * g_valsT[(b * SS + s) * HH + d];
        g_attn[(l * BB + b) * HH + d] = acc;
    }
}

// ---------------- host launcher ----------------
extern "C" void kernel_launch(void* const* d_in, const int* in_sizes, int n_in,
                              void* d_out, int out_size) {
    const float* img    = (const float*)d_in[0];
    const float* pooled = (const float*)d_in[1];
    const float* embed  = (const float*)d_in[2];
    const float* Wq     = (const float*)d_in[3];
    const float* bq     = (const float*)d_in[4];
    const float* Wk     = (const float*)d_in[5];
    const float* bk     = (const float*)d_in[6];
    const float* Wv     = (const float*)d_in[7];
    const float* bv     = (const float*)d_in[8];
    const float* Wih    = (const float*)d_in[9];
    const float* Whh    = (const float*)d_in[10];
    const float* bih    = (const float*)d_in[11];
    const float* bhh    = (const float*)d_in[12];
    const float* projW  = (const float*)d_in[13];
    const float* projb  = (const float*)d_in[14];
    const float* hattW  = (const float*)d_in[15];
    const float* hattb  = (const float*)d_in[16];
    const int*   sosp   = (const int*)d_in[17];
    float* res = (float*)d_out;

    k_kv<<<(BB * HH * SS) / 256, 256>>>(img, Wk, bk, Wv, bv);
    k_init<<<(LL * BB * HH) / 256, 256>>>(pooled, embed, sosp);

    // res[:, :, 0] from <SOS> embedding (no argmax)
    k_logits<<<157, 256>>>(0, projW, projb, res, 0, 0);

    for (int i = 0; i < TT - 1; ++i) {
        k_lstm<<<128, 512>>>(i == 0 ? 0 : 1, embed, Wih, Whh, bih, bhh, 0);
        k_lstm<<<128, 512>>>(2, embed, Wih, Whh, bih, bhh, 1);
        k_logits<<<157, 256>>>(1, projW, projb, res, i + 1, (i < TT - 2) ? 1 : 0);

        if (i < TT - 2) {
            k_gemm_tanh<0><<<dim3(32, LL), 256>>>(Wq, bq);
            k_attn<<<dim3(BB, LL), 256>>>();
            k_gemm_tanh<1><<<dim3(32, LL), 256>>>(hattW, hattb);
        }
    }
}

// round 10
// speedup vs baseline: 3.1531x; 1.1639x over previous
#include <cuda_runtime.h>
#include <cuda_bf16.h>
#include <cstdint>

// Problem constants
#define BB 32      // batch
#define HH 512     // hidden
#define LL 2       // lstm layers
#define TT 20      // text_max_len
#define VV 10000   // vocab
#define SS 49      // spatial (7x7)

// ---------------- device scratch (no allocation allowed) ----------------
__device__ float g_keysT[BB * SS * HH];   // keys  transposed: [b][s][d]
__device__ float g_valsT[BB * SS * HH];   // values transposed: [b][s][d]
__device__ float g_H1[LL * BB * HH];      // h after LSTM (pre-attention-update)
__device__ float g_H2[LL * BB * HH];      // h after attention gate (input to next LSTM)
__device__ float g_C [LL * BB * HH];      // cell state
__device__ float g_q [LL * BB * HH];      // attention query
__device__ float g_attn[LL * BB * HH];    // attention context
__device__ float g_pred0[BB * HH];        // <SOS> embedding
__device__ unsigned long long g_amax[BB]; // packed argmax keys

// ---------------- helpers ----------------
__device__ __forceinline__ float sigmoidf_(float x) { return 1.0f / (1.0f + expf(-x)); }

__device__ __forceinline__ unsigned long long pack_key(float val, int v) {
    unsigned u = __float_as_uint(val);
    u = (u & 0x80000000u) ? ~u : (u | 0x80000000u);   // order-preserving map
    return (((unsigned long long)u) << 32) | (unsigned)(~(unsigned)v);
}

// packed dual-fp32 FMA (sm_103a): acc(2xf32) += w(2xf32) * x(2xf32)
__device__ __forceinline__ void ffma2(unsigned long long &acc, unsigned long long w,
                                      float xlo, float xhi) {
    unsigned long long x;
    asm("mov.b64 %0, {%1, %2};" : "=l"(x) : "f"(xlo), "f"(xhi));
    asm("fma.rn.f32x2 %0, %1, %2, %0;" : "+l"(acc) : "l"(w), "l"(x));
}
__device__ __forceinline__ unsigned long long pack2(float lo, float hi) {
    unsigned long long o;
    asm("mov.b64 %0, {%1, %2};" : "=l"(o) : "f"(lo), "f"(hi));
    return o;
}
__device__ __forceinline__ float sum2(unsigned long long a) {
    float lo, hi;
    asm("mov.b64 {%0, %1}, %2;" : "=f"(lo), "=f"(hi) : "l"(a));
    return lo + hi;
}

// ---------------- K1: precompute keys/values (transposed) ----------------
__global__ void k_kv(const float* __restrict__ img,
                     const float* __restrict__ Wk, const float* __restrict__ bk,
                     const float* __restrict__ Wv, const float* __restrict__ bv) {
    __shared__ float wk_s[SS * SS];
    __shared__ float wv_s[SS * SS];
    for (int i = threadIdx.x; i < SS * SS; i += blockDim.x) {
        wk_s[i] = Wk[i];
        wv_s[i] = Wv[i];
    }
    __syncthreads();

    int idx = blockIdx.x * blockDim.x + threadIdx.x;
    int s = idx % SS;
    int d = (idx / SS) % HH;
    int b = idx / (SS * HH);

    const float* chan = img + (b * HH + d) * SS;
    float ak = 0.f, av = 0.f;
    #pragma unroll
    for (int sp = 0; sp < SS; ++sp) {
        float c = chan[sp];
        ak += c * wk_s[s * SS + sp];
        av += c * wv_s[s * SS + sp];
    }
    int o = (b * SS + s) * HH + d;
    g_keysT[o] = tanhf(ak + bk[s]);
    g_valsT[o] = tanhf(av + bv[s]);
}

// ---------------- K2: init state ----------------
__global__ void k_init(const float* __restrict__ pooled,
                       const float* __restrict__ embed,
                       const int* __restrict__ sos_ptr) {
    int idx = blockIdx.x * blockDim.x + threadIdx.x;
    int k = idx % HH;
    int b = (idx / HH) % BB;
    int l = idx / (HH * BB);
    float p = pooled[b * HH + k];
    g_H2[idx] = p;
    g_C[idx]  = p;
    if (l == 0) {
        int sos = sos_ptr[0];
        g_pred0[b * HH + k] = embed[sos * HH + k];
    }
    if (idx < BB) g_amax[idx] = 0ULL;
}

// ---------------- K3: logits GEMM (lane=row) + res write + fused argmax ----------------
// 313 blocks x 256 threads. Tile = 32 vocab rows, lane = row, acc[32 batches] packed.
// 8 warps k-split; 4 chunks of 128 k.
__global__ void k_logits(int src_sel,
                         const float* __restrict__ projW, const float* __restrict__ projb,
                         float* __restrict__ res, int t, int do_argmax) {
    __shared__ float4 xs4[32][33];                 // [b][q] acts chunk (128 k)
    __shared__ __align__(16) char buf[17536];      // ws4 [32][33] f4  /  red [8][32][17] f
    __shared__ unsigned long long skey[16][17];

    float4 (*ws4)[33] = (float4(*)[33])buf;
    float  (*red)[32][17] = (float(*)[32][17])buf;

    const float* x = src_sel ? (g_H1 + BB * HH) : g_pred0;

    int tid  = threadIdx.x;
    int warp = tid >> 5;
    int lane = tid & 31;                 // lane == vocab row within tile
    int v0   = blockIdx.x * 32;

    unsigned long long acc[32];
    #pragma unroll
    for (int b = 0; b < 32; ++b) acc[b] = 0ULL;

    for (int ch = 0; ch < 4; ++ch) {
        int k0 = ch * 128;
        // stage acts: 32 b x 32 quads = 1024 f4, 4/thread (coalesced)
        #pragma unroll
        for (int i = 0; i < 4; ++i) {
            int f = tid + i * 256;
            int b = f >> 5, q = f & 31;
            xs4[b][q] = *(const float4*)(x + b * HH + k0 + q * 4);
        }
        // stage weights: 32 rows x 32 quads = 1024 f4, 4/thread (coalesced)
        #pragma unroll
        for (int i = 0; i < 4; ++i) {
            int f = tid + i * 256;
            int r = f >> 5, q = f & 31;
            int v = v0 + r; if (v >= VV) v = VV - 1;
            ws4[r][q] = *(const float4*)(projW + v * HH + k0 + q * 4);
        }
        __syncthreads();

        #pragma unroll
        for (int qq = 0; qq < 4; ++qq) {
            int q = warp * 4 + qq;
            float4 w4 = ws4[lane][q];                 // wide, lane=row
            unsigned long long w01 = pack2(w4.x, w4.y);
            unsigned long long w23 = pack2(w4.z, w4.w);
            #pragma unroll
            for (int b = 0; b < 32; ++b) {
                float4 x4 = xs4[b][q];                // broadcast
                ffma2(acc[b], w01, x4.x, x4.y);
                ffma2(acc[b], w23, x4.z, x4.w);
            }
        }
        __syncthreads();
    }

    unsigned long long mybest = 0ULL;
    int myb = -1;

    // two batch-half passes through the reduction buffer
    for (int bh = 0; bh < 2; ++bh) {
        // each warp writes its partials for batches [bh*16, bh*16+16)
        #pragma unroll
        for (int bi = 0; bi < 16; ++bi)
            red[warp][lane][bi] = sum2(acc[bh * 16 + bi]);   // red[w][row][bi]
        __syncthreads();

        // 512 outputs (32 rows x 16 b): 2 per thread
        #pragma unroll
        for (int rep = 0; rep < 2; ++rep) {
            int p = tid + rep * 256;
            int bi = p & 15, row = p >> 4;
            float val = 0.f;
            #pragma unroll
            for (int w = 0; w < 8; ++w) val += red[w][row][bi];
            int v = v0 + row;
            int b = bh * 16 + bi;
            if (v < VV) {
                val += projb[v];
                res[b * (VV * TT) + v * TT + t] = val;
                if (do_argmax) {
                    unsigned long long key = pack_key(val, v);
                    if (key > mybest) mybest = key;
                }
            }
            myb = b;   // both reps share the same b
        }
        __syncthreads();

        if (do_argmax) {
            skey[tid & 15][tid >> 4] = mybest;
            __syncthreads();
            if (tid < 16) {
                unsigned long long m = 0ULL;
                #pragma unroll
                for (int r = 0; r < 16; ++r) {
                    unsigned long long k2 = skey[tid][r];
                    if (k2 > m) m = k2;
                }
                if (m) atomicMax(&g_amax[bh * 16 + tid], m);
            }
            __syncthreads();
            mybest = 0ULL;
        }
    }
    (void)myb;
}

// ---------------- K4: LSTM cell (one layer), lane=row, fused finalize ----------------
// 128 blocks x 256 threads. Tile = 4 units x 4 gates = 16 rows.
// lane -> (j = lane&15 row, bh = lane>>4 batch half); acc[16] packed over k-pairs.
// K = 1024 concat (x: chunks 0-3, h: chunks 4-7), 8 warps split each 128-k chunk.
// xsel: 0 -> g_pred0 ; 1 -> embed[argmax] ; 2 -> g_H1 layer 0
__global__ void k_lstm(int layer, int xsel, const float* __restrict__ embed,
                       const float* __restrict__ Wih, const float* __restrict__ Whh,
                       const float* __restrict__ bih, const float* __restrict__ bhh) {
    __shared__ float4 xs4[32][33];     // [b][q] acts chunk (128 k)
    __shared__ float4 ws4[16][33];     // [row j][q]
    __shared__ float  red[8][32][17];  // [warp][b][j]
    __shared__ float  gv[16][33];      // [j][b] gate pre-activations
    __shared__ int    vsel[BB];

    int tid  = threadIdx.x;   // 256
    int warp = tid >> 5;
    int lane = tid & 31;
    int j    = lane & 15;     // row within tile
    int bh   = lane >> 4;     // batch half
    int tile = blockIdx.x;    // 0..127 -> units tile*4 .. tile*4+3

    // reset argmax between steps (layer1 runs after all layer0 reads, before next logits)
    if (layer == 1 && blockIdx.x == 0 && tid < BB) g_amax[tid] = 0ULL;
    if (xsel == 1 && tid < BB) vsel[tid] = (int)(~(unsigned)(g_amax[tid] & 0xffffffffULL));
    __syncthreads();

    const float* h_prev = g_H2 + layer * BB * HH;
    const float* x_base = (xsel == 2) ? g_H1 : g_pred0;
    const float* WihL = Wih + layer * 4 * HH * HH;
    const float* WhhL = Whh + layer * 4 * HH * HH;

    unsigned long long acc[16];
    #pragma unroll
    for (int bi = 0; bi < 16; ++bi) acc[bi] = 0ULL;

    for (int ch = 0; ch < 8; ++ch) {
        int mat = ch >> 2;                 // 0 = x/Wih, 1 = h/Whh
        int k0  = (ch & 3) * 128;
        const float* wbase = mat ? WhhL : WihL;

        // stage acts: 1024 f4, 4/thread
        #pragma unroll
        for (int i = 0; i < 4; ++i) {
            int f = tid + i * 256;
            int b = f >> 5, q = f & 31;
            const float* src;
            if (mat) src = h_prev + b * HH;
            else if (xsel == 1) src = embed + (size_t)vsel[b] * HH;
            else src = x_base + b * HH;
            xs4[b][q] = *(const float4*)(src + k0 + q * 4);
        }
        // stage weights: 16 rows x 32 quads = 512 f4, 2/thread
        #pragma unroll
        for (int i = 0; i < 2; ++i) {
            int f = tid + i * 256;
            int r = f >> 5, q = f & 31;          // r = j row
            int uu = r >> 2, g = r & 3;
            int grow = g * HH + tile * 4 + uu;   // row in [4H, H] matrix
            ws4[r][q] = *(const float4*)(wbase + (size_t)grow * HH + k0 + q * 4);
        }
        __syncthreads();

        #pragma unroll
        for (int qq = 0; qq < 4; ++qq) {
            int q = warp * 4 + qq;
            float4 w4 = ws4[j][q];                    // 16 distinct + dup across bh
            unsigned long long w01 = pack2(w4.x, w4.y);
            unsigned long long w23 = pack2(w4.z, w4.w);
            #pragma unroll
            for (int bi = 0; bi < 16; ++bi) {
                float4 x4 = xs4[bh * 16 + bi][q];     // 2-address broadcast
                ffma2(acc[bi], w01, x4.x, x4.y);
                ffma2(acc[bi], w23, x4.z, x4.w);
            }
        }
        __syncthreads();
    }

    // reduction over warps (k-slices)
    #pragma unroll
    for (int bi = 0; bi < 16; ++bi)
        red[warp][bh * 16 + bi][j] = sum2(acc[bi]);
    __syncthreads();

    // gate pre-activations: 512 outputs, 2 per thread
    #pragma unroll
    for (int rep = 0; rep < 2; ++rep) {
        int p = tid + rep * 256;
        int b = p & 31, jj = p >> 5;      // jj 0..15
        float val = 0.f;
        #pragma unroll
        for (int w = 0; w < 8; ++w) val += red[w][b][jj];
        int uu = jj >> 2, g = jj & 3;
        int grow = g * HH + tile * 4 + uu;
        val += bih[layer * 4 * HH + grow] + bhh[layer * 4 * HH + grow];
        gv[jj][b] = val;
    }
    __syncthreads();

    // finalize: 128 (b, unit) pairs
    if (tid < 128) {
        int b = tid & 31, uu = tid >> 5;
        float vi = gv[uu * 4 + 0][b];
        float vf = gv[uu * 4 + 1][b];
        float vg = gv[uu * 4 + 2][b];
        float vo = gv[uu * 4 + 3][b];
        int u = tile * 4 + uu;
        int co = layer * BB * HH + b * HH + u;
        float c2 = sigmoidf_(vf) * g_C[co] + sigmoidf_(vi) * tanhf(vg);
        g_C[co]  = c2;
        g_H1[co] = sigmoidf_(vo) * tanhf(c2);
    }
}

// ---------------- K5: 32xN (N=512) GEMM + tanh (unchanged from R8) ----------------
template <int MODE>
__global__ void k_gemm_tanh(const float* __restrict__ W1, const float* __restrict__ bias) {
    __shared__ float4 as4[32][17];
    __shared__ float4 bs4[32][17];
    __shared__ float4 wt[16][2][16];

    int l    = blockIdx.y;
    int tid  = threadIdx.x;    // 256
    int warp = tid >> 5;
    int lane = tid & 31;       // batch
    int j0   = blockIdx.x * 16;

    const float* A  = (MODE ? g_attn : g_H1) + l * BB * HH;
    const float* Bm = g_H1 + l * BB * HH;
    float*      out = (MODE ? g_H2 : g_q) + l * BB * HH;
    const int WS = MODE ? 2 * HH : HH;

    float4 acc[2];
    acc[0] = make_float4(0.f, 0.f, 0.f, 0.f);
    acc[1] = make_float4(0.f, 0.f, 0.f, 0.f);

    for (int kt = 0; kt < 8; ++kt) {
        int k0 = kt * 64;
        #pragma unroll
        for (int i = 0; i < 2; ++i) {
            int fid = tid + i * 256;
            int b = fid >> 4, q = fid & 15;
            as4[b][q] = *(const float4*)(A + b * HH + k0 + q * 4);
            if (MODE) bs4[b][q] = *(const float4*)(Bm + b * HH + k0 + q * 4);
        }
        {
            int r = tid >> 4, c = tid & 15;
            wt[r][0][c] = *(const float4*)(W1 + (j0 + r) * WS + k0 + c * 4);
            if (MODE) wt[r][1][c] = *(const float4*)(W1 + (j0 + r) * WS + HH + k0 + c * 4);
        }
        __syncthreads();

        int jr = warp * 2;
        #pragma unroll
        for (int q = 0; q < 16; ++q) {
            float4 av = as4[lane][q];
            float4 bv;
            if (MODE) bv = bs4[lane][q];
            #pragma unroll
            for (int jj = 0; jj < 2; ++jj) {
                float4 w = wt[jr + jj][0][q];
                acc[jj].x += w.x * av.x;  acc[jj].y += w.y * av.y;
                acc[jj].z += w.z * av.z;  acc[jj].w += w.w * av.w;
                if (MODE) {
                    float4 w2 = wt[jr + jj][1][q];
                    acc[jj].x += w2.x * bv.x;  acc[jj].y += w2.y * bv.y;
                    acc[jj].z += w2.z * bv.z;  acc[jj].w += w2.w * bv.w;
                }
            }
        }
        __syncthreads();
    }

    #pragma unroll
    for (int jj = 0; jj < 2; ++jj) {
        int jdx = j0 + warp * 2 + jj;
        float s = (acc[jj].x + acc[jj].y) + (acc[jj].z + acc[jj].w);
        out[lane * HH + jdx] = tanhf(s + bias[jdx]);
    }
}

// ---------------- K6: attention scores + softmax + context (unchanged) ----------------
__global__ void k_attn() {
    __shared__ float qs[HH];
    __shared__ float ssh[SS];
    __shared__ float wsh[SS];

    int b = blockIdx.x;
    int l = blockIdx.y;
    int tid = threadIdx.x;     // 256
    int warp = tid >> 5;
    int lane = tid & 31;

    qs[tid]       = g_q[(l * BB + b) * HH + tid];
    qs[tid + 256] = g_q[(l * BB + b) * HH + tid + 256];
    __syncthreads();

    for (int s = warp; s < SS; s += 8) {
        const float* krow = g_keysT + (b * SS + s) * HH;
        float sum = 0.f;
        #pragma unroll
        for (int i = 0; i < 4; ++i) {
            float4 kv = *(const float4*)(krow + lane * 4 + i * 128);
            float4 qv = *(const float4*)(qs   + lane * 4 + i * 128);
            sum += kv.x*qv.x + kv.y*qv.y + kv.z*qv.z + kv.w*qv.w;
        }
        #pragma unroll
        for (int off = 16; off; off >>= 1)
            sum += __shfl_xor_sync(0xffffffffu, sum, off);
        if (lane == 0) ssh[s] = sum / 7.0f;
    }
    __syncthreads();

    if (tid < 32) {
        float v0 = ssh[tid];
        float v1 = (tid + 32 < SS) ? ssh[tid + 32] : -3.4e38f;
        float m = fmaxf(v0, v1);
        #pragma unroll
        for (int off = 16; off; off >>= 1)
            m = fmaxf(m, __shfl_xor_sync(0xffffffffu, m, off));
        float e0 = expf(v0 - m);
        float e1 = (tid + 32 < SS) ? expf(v1 - m) : 0.f;
        float s = e0 + e1;
        #pragma unroll
        for (int off = 16; off; off >>= 1)
            s += __shfl_xor_sync(0xffffffffu, s, off);
        wsh[tid] = e0 / s;
        if (tid + 32 < SS) wsh[tid + 32] = e1 / s;
    }
    __syncthreads();

    #pragma unroll
    for (int r = 0; r < 2; ++r) {
        int d = tid + r * 256;
        float acc = 0.f;
        #pragma unroll
        for (int s = 0; s < SS; ++s)
            acc += wsh[s] * g_valsT[(b * SS + s) * HH + d];
        g_attn[(l * BB + b) * HH + d] = acc;
    }
}

// ---------------- host launcher ----------------
extern "C" void kernel_launch(void* const* d_in, const int* in_sizes, int n_in,
                              void* d_out, int out_size) {
    const float* img    = (const float*)d_in[0];
    const float* pooled = (const float*)d_in[1];
    const float* embed  = (const float*)d_in[2];
    const float* Wq     = (const float*)d_in[3];
    const float* bq     = (const float*)d_in[4];
    const float* Wk     = (const float*)d_in[5];
    const float* bk     = (const float*)d_in[6];
    const float* Wv     = (const float*)d_in[7];
    const float* bv     = (const float*)d_in[8];
    const float* Wih    = (const float*)d_in[9];
    const float* Whh    = (const float*)d_in[10];
    const float* bih    = (const float*)d_in[11];
    const float* bhh    = (const float*)d_in[12];
    const float* projW  = (const float*)d_in[13];
    const float* projb  = (const float*)d_in[14];
    const float* hattW  = (const float*)d_in[15];
    const float* hattb  = (const float*)d_in[16];
    const int*   sosp   = (const int*)d_in[17];
    float* res = (float*)d_out;

    k_kv<<<(BB * HH * SS) / 256, 256>>>(img, Wk, bk, Wv, bv);
    k_init<<<(LL * BB * HH) / 256, 256>>>(pooled, embed, sosp);

    // res[:, :, 0] from <SOS> embedding (no argmax)
    k_logits<<<313, 256>>>(0, projW, projb, res, 0, 0);

    for (int i = 0; i < TT - 1; ++i) {
        k_lstm<<<128, 256>>>(0, i == 0 ? 0 : 1, embed, Wih, Whh, bih, bhh);
        k_lstm<<<128, 256>>>(1, 2, embed, Wih, Whh, bih, bhh);
        k_logits<<<313, 256>>>(1, projW, projb, res, i + 1, (i < TT - 2) ? 1 : 0);

        if (i < TT - 2) {
            k_gemm_tanh<0><<<dim3(32, LL), 256>>>(Wq, bq);
            k_attn<<<dim3(BB, LL), 256>>>();
            k_gemm_tanh<1><<<dim3(32, LL), 256>>>(hattW, hattb);
        }
    }
}

// round 11
// speedup vs baseline: 3.4775x; 1.1029x over previous
#include <cuda_runtime.h>
#include <cuda_bf16.h>
#include <cstdint>

// Problem constants
#define BB 32      // batch
#define HH 512     // hidden
#define LL 2       // lstm layers
#define TT 20      // text_max_len
#define VV 10000   // vocab
#define SS 49      // spatial (7x7)

// ---------------- device scratch (no allocation allowed) ----------------
__device__ float g_keysT[BB * SS * HH];   // keys  transposed: [b][s][d]
__device__ float g_valsT[BB * SS * HH];   // values transposed: [b][s][d]
__device__ float g_H1[LL * BB * HH];      // h after LSTM (pre-attention-update)
__device__ float g_H2[LL * BB * HH];      // h after attention gate (input to next LSTM)
__device__ float g_C [LL * BB * HH];      // cell state
__device__ float g_q [LL * BB * HH];      // attention query
__device__ float g_attn[LL * BB * HH];    // attention context
__device__ float g_pred0[BB * HH];        // <SOS> embedding
__device__ unsigned long long g_amax[BB]; // packed argmax keys

// ---------------- helpers ----------------
__device__ __forceinline__ float sigmoidf_(float x) { return 1.0f / (1.0f + expf(-x)); }

__device__ __forceinline__ unsigned long long pack_key(float val, int v) {
    unsigned u = __float_as_uint(val);
    u = (u & 0x80000000u) ? ~u : (u | 0x80000000u);   // order-preserving map
    return (((unsigned long long)u) << 32) | (unsigned)(~(unsigned)v);
}

// packed dual-fp32 FMA, no packing movs: operands already packed in b64
__device__ __forceinline__ void ffma2p(unsigned long long &acc,
                                       unsigned long long w, unsigned long long x) {
    asm("fma.rn.f32x2 %0, %1, %2, %0;" : "+l"(acc) : "l"(w), "l"(x));
}
__device__ __forceinline__ float sum2(unsigned long long a) {
    float lo, hi;
    asm("mov.b64 {%0, %1}, %2;" : "=f"(lo), "=f"(hi) : "l"(a));
    return lo + hi;
}

// ---------------- K1: precompute keys/values (transposed) ----------------
__global__ void k_kv(const float* __restrict__ img,
                     const float* __restrict__ Wk, const float* __restrict__ bk,
                     const float* __restrict__ Wv, const float* __restrict__ bv) {
    __shared__ float wk_s[SS * SS];
    __shared__ float wv_s[SS * SS];
    for (int i = threadIdx.x; i < SS * SS; i += blockDim.x) {
        wk_s[i] = Wk[i];
        wv_s[i] = Wv[i];
    }
    __syncthreads();

    int idx = blockIdx.x * blockDim.x + threadIdx.x;
    int s = idx % SS;
    int d = (idx / SS) % HH;
    int b = idx / (SS * HH);

    const float* chan = img + (b * HH + d) * SS;
    float ak = 0.f, av = 0.f;
    #pragma unroll
    for (int sp = 0; sp < SS; ++sp) {
        float c = chan[sp];
        ak += c * wk_s[s * SS + sp];
        av += c * wv_s[s * SS + sp];
    }
    int o = (b * SS + s) * HH + d;
    g_keysT[o] = tanhf(ak + bk[s]);
    g_valsT[o] = tanhf(av + bv[s]);
}

// ---------------- K2: init state ----------------
__global__ void k_init(const float* __restrict__ pooled,
                       const float* __restrict__ embed,
                       const int* __restrict__ sos_ptr) {
    int idx = blockIdx.x * blockDim.x + threadIdx.x;
    int k = idx % HH;
    int b = (idx / HH) % BB;
    int l = idx / (HH * BB);
    float p = pooled[b * HH + k];
    g_H2[idx] = p;
    g_C[idx]  = p;
    if (l == 0) {
        int sos = sos_ptr[0];
        g_pred0[b * HH + k] = embed[sos * HH + k];
    }
    if (idx < BB) g_amax[idx] = 0ULL;
}

// ---------------- K3: logits GEMM, pipelined, lane=row ----------------
// 313 blocks x 256 threads. Tile = 32 vocab rows, lane = row, acc[32 batches].
// 4 k-chunks of 128, double-buffered smem, register prefetch of chunk c+1.
__global__ void __launch_bounds__(256)
k_logits(int src_sel,
         const float* __restrict__ projW, const float* __restrict__ projb,
         float* __restrict__ res, int t, int do_argmax) {
    __shared__ float4 xs4[2][32][33];              // [buf][b][q]
    __shared__ float4 ws4[2][32][33];              // [buf][row][q]
    __shared__ float  red[8][32][17];              // [warp][row][bi]
    __shared__ unsigned long long skey[16][17];

    const float* x = src_sel ? (g_H1 + BB * HH) : g_pred0;

    int tid  = threadIdx.x;
    int warp = tid >> 5;
    int lane = tid & 31;                 // lane == vocab row within tile
    int v0   = blockIdx.x * 32;

    unsigned long long acc[32];
    #pragma unroll
    for (int b = 0; b < 32; ++b) acc[b] = 0ULL;

    // prefetch chunk 0: each thread loads (b = warp+8i, q = lane) and (r = warp+8i, q = lane)
    float4 ra[4], rw[4];
    #pragma unroll
    for (int i = 0; i < 4; ++i) {
        int b = warp + 8 * i;
        ra[i] = *(const float4*)(x + b * HH + lane * 4);
        int v = v0 + b; if (v >= VV) v = VV - 1;
        rw[i] = *(const float4*)(projW + (size_t)v * HH + lane * 4);
    }

    for (int ch = 0; ch < 4; ++ch) {
        int p = ch & 1;
        #pragma unroll
        for (int i = 0; i < 4; ++i) {
            int r = warp + 8 * i;
            xs4[p][r][lane] = ra[i];
            ws4[p][r][lane] = rw[i];
        }
        if (ch < 3) {
            int k0 = (ch + 1) * 128;
            #pragma unroll
            for (int i = 0; i < 4; ++i) {
                int b = warp + 8 * i;
                ra[i] = *(const float4*)(x + b * HH + k0 + lane * 4);
                int v = v0 + b; if (v >= VV) v = VV - 1;
                rw[i] = *(const float4*)(projW + (size_t)v * HH + k0 + lane * 4);
            }
        }
        __syncthreads();

        #pragma unroll
        for (int qq = 0; qq < 4; ++qq) {
            int q = warp * 4 + qq;
            ulonglong2 w = *reinterpret_cast<const ulonglong2*>(&ws4[p][lane][q]);
            #pragma unroll
            for (int b = 0; b < 32; ++b) {
                ulonglong2 xv = *reinterpret_cast<const ulonglong2*>(&xs4[p][b][q]);
                ffma2p(acc[b], w.x, xv.x);
                ffma2p(acc[b], w.y, xv.y);
            }
        }
        __syncthreads();
    }

    unsigned long long mybest = 0ULL;

    for (int bh = 0; bh < 2; ++bh) {
        #pragma unroll
        for (int bi = 0; bi < 16; ++bi)
            red[warp][lane][bi] = sum2(acc[bh * 16 + bi]);
        __syncthreads();

        #pragma unroll
        for (int rep = 0; rep < 2; ++rep) {
            int p = tid + rep * 256;
            int bi = p & 15, row = p >> 4;
            float val = 0.f;
            #pragma unroll
            for (int w = 0; w < 8; ++w) val += red[w][row][bi];
            int v = v0 + row;
            int b = bh * 16 + bi;
            if (v < VV) {
                val += projb[v];
                res[b * (VV * TT) + v * TT + t] = val;
                if (do_argmax) {
                    unsigned long long key = pack_key(val, v);
                    if (key > mybest) mybest = key;
                }
            }
        }
        __syncthreads();

        if (do_argmax) {
            skey[tid & 15][tid >> 4] = mybest;
            __syncthreads();
            if (tid < 16) {
                unsigned long long m = 0ULL;
                #pragma unroll
                for (int r = 0; r < 16; ++r) {
                    unsigned long long k2 = skey[tid][r];
                    if (k2 > m) m = k2;
                }
                if (m) atomicMax(&g_amax[bh * 16 + tid], m);
            }
            __syncthreads();
            mybest = 0ULL;
        }
    }
}

// ---------------- K4: LSTM cell, pipelined, lane=row, fused finalize ----------------
// 128 blocks x 256 threads. Tile = 4 units x 4 gates = 16 rows.
// lane -> (j = lane&15 row, bh = lane>>4 batch half); acc[16] packed.
// 8 chunks (x: 0-3 via Wih, h: 4-7 via Whh), double-buffered + reg prefetch.
__global__ void __launch_bounds__(256)
k_lstm(int layer, int xsel, const float* __restrict__ embed,
       const float* __restrict__ Wih, const float* __restrict__ Whh,
       const float* __restrict__ bih, const float* __restrict__ bhh) {
    __shared__ float4 xs4[2][32][33];   // [buf][b][q]
    __shared__ float4 ws4[2][16][33];   // [buf][row j][q]
    __shared__ float  red[8][32][17];   // [warp][b][j]
    __shared__ float  gv[16][33];       // [j][b]
    __shared__ int    vsel[BB];

    int tid  = threadIdx.x;   // 256
    int warp = tid >> 5;
    int lane = tid & 31;
    int j    = lane & 15;     // row within tile
    int bh   = lane >> 4;     // batch half
    int tile = blockIdx.x;

    if (layer == 1 && blockIdx.x == 0 && tid < BB) g_amax[tid] = 0ULL;
    if (xsel == 1 && tid < BB) vsel[tid] = (int)(~(unsigned)(g_amax[tid] & 0xffffffffULL));
    __syncthreads();

    const float* h_prev = g_H2 + layer * BB * HH;
    const float* x_base = (xsel == 2) ? g_H1 : g_pred0;
    const float* WihL = Wih + (size_t)layer * 4 * HH * HH;
    const float* WhhL = Whh + (size_t)layer * 4 * HH * HH;

    unsigned long long acc[16];
    #pragma unroll
    for (int bi = 0; bi < 16; ++bi) acc[bi] = 0ULL;

    // per-thread load coords: acts (b = warp+8i, q = lane), weights (r = warp+8i, c = lane)
    float4 ra[4], rw[2];
    {   // prefetch chunk 0 (mat = x, k0 = 0)
        #pragma unroll
        for (int i = 0; i < 4; ++i) {
            int b = warp + 8 * i;
            const float* src = (xsel == 1) ? (embed + (size_t)vsel[b] * HH)
                                           : (x_base + b * HH);
            ra[i] = *(const float4*)(src + lane * 4);
        }
        #pragma unroll
        for (int i = 0; i < 2; ++i) {
            int r = warp + 8 * i;
            int grow = (r & 3) * HH + tile * 4 + (r >> 2);
            rw[i] = *(const float4*)(WihL + (size_t)grow * HH + lane * 4);
        }
    }

    for (int ch = 0; ch < 8; ++ch) {
        int p = ch & 1;
        #pragma unroll
        for (int i = 0; i < 4; ++i) xs4[p][warp + 8 * i][lane] = ra[i];
        #pragma unroll
        for (int i = 0; i < 2; ++i) ws4[p][warp + 8 * i][lane] = rw[i];

        if (ch < 7) {
            int nmat = (ch + 1) >> 2;
            int nk0  = ((ch + 1) & 3) * 128;
            const float* wb = nmat ? WhhL : WihL;
            #pragma unroll
            for (int i = 0; i < 4; ++i) {
                int b = warp + 8 * i;
                const float* src;
                if (nmat) src = h_prev + b * HH;
                else if (xsel == 1) src = embed + (size_t)vsel[b] * HH;
                else src = x_base + b * HH;
                ra[i] = *(const float4*)(src + nk0 + lane * 4);
            }
            #pragma unroll
            for (int i = 0; i < 2; ++i) {
                int r = warp + 8 * i;
                int grow = (r & 3) * HH + tile * 4 + (r >> 2);
                rw[i] = *(const float4*)(wb + (size_t)grow * HH + nk0 + lane * 4);
            }
        }
        __syncthreads();

        #pragma unroll
        for (int qq = 0; qq < 4; ++qq) {
            int q = warp * 4 + qq;
            ulonglong2 w = *reinterpret_cast<const ulonglong2*>(&ws4[p][j][q]);
            #pragma unroll
            for (int bi = 0; bi < 16; ++bi) {
                ulonglong2 xv = *reinterpret_cast<const ulonglong2*>(&xs4[p][bh * 16 + bi][q]);
                ffma2p(acc[bi], w.x, xv.x);
                ffma2p(acc[bi], w.y, xv.y);
            }
        }
        __syncthreads();
    }

    #pragma unroll
    for (int bi = 0; bi < 16; ++bi)
        red[warp][bh * 16 + bi][j] = sum2(acc[bi]);
    __syncthreads();

    #pragma unroll
    for (int rep = 0; rep < 2; ++rep) {
        int p = tid + rep * 256;
        int b = p & 31, jj = p >> 5;      // jj 0..15
        float val = 0.f;
        #pragma unroll
        for (int w = 0; w < 8; ++w) val += red[w][b][jj];
        int grow = (jj & 3) * HH + tile * 4 + (jj >> 2);
        val += bih[layer * 4 * HH + grow] + bhh[layer * 4 * HH + grow];
        gv[jj][b] = val;
    }
    __syncthreads();

    if (tid < 128) {
        int b = tid & 31, uu = tid >> 5;
        float vi = gv[uu * 4 + 0][b];
        float vf = gv[uu * 4 + 1][b];
        float vg = gv[uu * 4 + 2][b];
        float vo = gv[uu * 4 + 3][b];
        int u = tile * 4 + uu;
        int co = layer * BB * HH + b * HH + u;
        float c2 = sigmoidf_(vf) * g_C[co] + sigmoidf_(vi) * tanhf(vg);
        g_C[co]  = c2;
        g_H1[co] = sigmoidf_(vo) * tanhf(c2);
    }
}

// ---------------- K5: 32xN (N=512) GEMM + tanh ----------------
template <int MODE>
__global__ void k_gemm_tanh(const float* __restrict__ W1, const float* __restrict__ bias) {
    __shared__ float4 as4[32][17];
    __shared__ float4 bs4[32][17];
    __shared__ float4 wt[16][2][16];

    int l    = blockIdx.y;
    int tid  = threadIdx.x;    // 256
    int warp = tid >> 5;
    int lane = tid & 31;       // batch
    int j0   = blockIdx.x * 16;

    const float* A  = (MODE ? g_attn : g_H1) + l * BB * HH;
    const float* Bm = g_H1 + l * BB * HH;
    float*      out = (MODE ? g_H2 : g_q) + l * BB * HH;
    const int WS = MODE ? 2 * HH : HH;

    float4 acc[2];
    acc[0] = make_float4(0.f, 0.f, 0.f, 0.f);
    acc[1] = make_float4(0.f, 0.f, 0.f, 0.f);

    for (int kt = 0; kt < 8; ++kt) {
        int k0 = kt * 64;
        #pragma unroll
        for (int i = 0; i < 2; ++i) {
            int fid = tid + i * 256;
            int b = fid >> 4, q = fid & 15;
            as4[b][q] = *(const float4*)(A + b * HH + k0 + q * 4);
            if (MODE) bs4[b][q] = *(const float4*)(Bm + b * HH + k0 + q * 4);
        }
        {
            int r = tid >> 4, c = tid & 15;
            wt[r][0][c] = *(const float4*)(W1 + (j0 + r) * WS + k0 + c * 4);
            if (MODE) wt[r][1][c] = *(const float4*)(W1 + (j0 + r) * WS + HH + k0 + c * 4);
        }
        __syncthreads();

        int jr = warp * 2;
        #pragma unroll
        for (int q = 0; q < 16; ++q) {
            float4 av = as4[lane][q];
            float4 bv;
            if (MODE) bv = bs4[lane][q];
            #pragma unroll
            for (int jj = 0; jj < 2; ++jj) {
                float4 w = wt[jr + jj][0][q];
                acc[jj].x += w.x * av.x;  acc[jj].y += w.y * av.y;
                acc[jj].z += w.z * av.z;  acc[jj].w += w.w * av.w;
                if (MODE) {
                    float4 w2 = wt[jr + jj][1][q];
                    acc[jj].x += w2.x * bv.x;  acc[jj].y += w2.y * bv.y;
                    acc[jj].z += w2.z * bv.z;  acc[jj].w += w2.w * bv.w;
                }
            }
        }
        __syncthreads();
    }

    #pragma unroll
    for (int jj = 0; jj < 2; ++jj) {
        int jdx = j0 + warp * 2 + jj;
        float s = (acc[jj].x + acc[jj].y) + (acc[jj].z + acc[jj].w);
        out[lane * HH + jdx] = tanhf(s + bias[jdx]);
    }
}

// ---------------- K6: attention scores + softmax + context ----------------
__global__ void k_attn() {
    __shared__ float qs[HH];
    __shared__ float ssh[SS];
    __shared__ float wsh[SS];

    int b = blockIdx.x;
    int l = blockIdx.y;
    int tid = threadIdx.x;     // 256
    int warp = tid >> 5;
    int lane = tid & 31;

    qs[tid]       = g_q[(l * BB + b) * HH + tid];
    qs[tid + 256] = g_q[(l * BB + b) * HH + tid + 256];
    __syncthreads();

    for (int s = warp; s < SS; s += 8) {
        const float* krow = g_keysT + (b * SS + s) * HH;
        float sum = 0.f;
        #pragma unroll
        for (int i = 0; i < 4; ++i) {
            float4 kv = *(const float4*)(krow + lane * 4 + i * 128);
            float4 qv = *(const float4*)(qs   + lane * 4 + i * 128);
            sum += kv.x*qv.x + kv.y*qv.y + kv.z*qv.z + kv.w*qv.w;
        }
        #pragma unroll
        for (int off = 16; off; off >>= 1)
            sum += __shfl_xor_sync(0xffffffffu, sum, off);
        if (lane == 0) ssh[s] = sum / 7.0f;
    }
    __syncthreads();

    if (tid < 32) {
        float v0 = ssh[tid];
        float v1 = (tid + 32 < SS) ? ssh[tid + 32] : -3.4e38f;
        float m = fmaxf(v0, v1);
        #pragma unroll
        for (int off = 16; off; off >>= 1)
            m = fmaxf(m, __shfl_xor_sync(0xffffffffu, m, off));
        float e0 = expf(v0 - m);
        float e1 = (tid + 32 < SS) ? expf(v1 - m) : 0.f;
        float s = e0 + e1;
        #pragma unroll
        for (int off = 16; off; off >>= 1)
            s += __shfl_xor_sync(0xffffffffu, s, off);
        wsh[tid] = e0 / s;
        if (tid + 32 < SS) wsh[tid + 32] = e1 / s;
    }
    __syncthreads();

    #pragma unroll
    for (int r = 0; r < 2; ++r) {
        int d = tid + r * 256;
        float acc = 0.f;
        #pragma unroll
        for (int s = 0; s < SS; ++s)
            acc += wsh[s] * g_valsT[(b * SS + s) * HH + d];
        g_attn[(l * BB + b) * HH + d] = acc;
    }
}

// ---------------- host launcher ----------------
extern "C" void kernel_launch(void* const* d_in, const int* in_sizes, int n_in,
                              void* d_out, int out_size) {
    const float* img    = (const float*)d_in[0];
    const float* pooled = (const float*)d_in[1];
    const float* embed  = (const float*)d_in[2];
    const float* Wq     = (const float*)d_in[3];
    const float* bq     = (const float*)d_in[4];
    const float* Wk     = (const float*)d_in[5];
    const float* bk     = (const float*)d_in[6];
    const float* Wv     = (const float*)d_in[7];
    const float* bv     = (const float*)d_in[8];
    const float* Wih    = (const float*)d_in[9];
    const float* Whh    = (const float*)d_in[10];
    const float* bih    = (const float*)d_in[11];
    const float* bhh    = (const float*)d_in[12];
    const float* projW  = (const float*)d_in[13];
    const float* projb  = (const float*)d_in[14];
    const float* hattW  = (const float*)d_in[15];
    const float* hattb  = (const float*)d_in[16];
    const int*   sosp   = (const int*)d_in[17];
    float* res = (float*)d_out;

    k_kv<<<(BB * HH * SS) / 256, 256>>>(img, Wk, bk, Wv, bv);
    k_init<<<(LL * BB * HH) / 256, 256>>>(pooled, embed, sosp);

    // res[:, :, 0] from <SOS> embedding (no argmax)
    k_logits<<<313, 256>>>(0, projW, projb, res, 0, 0);

    for (int i = 0; i < TT - 1; ++i) {
        k_lstm<<<128, 256>>>(0, i == 0 ? 0 : 1, embed, Wih, Whh, bih, bhh);
        k_lstm<<<128, 256>>>(1, 2, embed, Wih, Whh, bih, bhh);
        k_logits<<<313, 256>>>(1, projW, projb, res, i + 1, (i < TT - 2) ? 1 : 0);

        if (i < TT - 2) {
            k_gemm_tanh<0><<<dim3(32, LL), 256>>>(Wq, bq);
            k_attn<<<dim3(BB, LL), 256>>>();
            k_gemm_tanh<1><<<dim3(32, LL), 256>>>(hattW, hattb);
        }
    }
}